// round 1
// baseline (speedup 1.0000x reference)
#include <cuda_runtime.h>
#include <math.h>

// Problem constants (fixed by the dataset)
#define T_TOKENS 16384
#define D_MODEL  4096
#define N_EXP    128

// GEMM tiling
#define BM 128
#define BN 128
#define BK 32
#define TPB 256

// Global scratch (allocation-free rule: __device__ globals)
__device__ float g_me[N_EXP];
__device__ int   g_ce[N_EXP];

__global__ void init_kernel() {
    int i = threadIdx.x;
    if (i < N_EXP) { g_me[i] = 0.0f; g_ce[i] = 0; }
}

// Maintain (v1,i1) >= (v2,i2); ties -> smaller index first (jax top_k semantics)
__device__ __forceinline__ void top2_upd(float& v1, int& i1, float& v2, int& i2,
                                         float v, int i) {
    if (v > v1 || (v == v1 && i < i1)) {
        v2 = v1; i2 = i1;
        v1 = v;  i1 = i;
    } else if (v > v2 || (v == v2 && i < i2)) {
        v2 = v; i2 = i;
    }
}

__global__ void __launch_bounds__(TPB, 1)
gate_kernel(const float* __restrict__ A,   // inp [T, D]
            const float* __restrict__ B,   // wg  [E, D]
            float* __restrict__ out) {
    extern __shared__ float sm[];
    float* As  = sm;             // [BK][BM]  (16 KB)
    float* Bs  = sm + BK * BM;   // [BK][BN]  (16 KB)
    float* Ls  = sm;             // [BM][BN]  (64 KB) — aliases As/Bs, used after GEMM
    float* sMe = sm + BM * BN;   // [128] local me accumulator

    const int tid = threadIdx.x;
    if (tid < N_EXP) sMe[tid] = 0.0f;

    const int ty   = tid >> 4;      // 0..15 -> token group (8 tokens)
    const int tx   = tid & 15;      // 0..15 -> expert group (8 experts)
    const int row0 = blockIdx.x * BM;

    float acc[8][8];
#pragma unroll
    for (int i = 0; i < 8; i++)
#pragma unroll
        for (int j = 0; j < 8; j++) acc[i][j] = 0.0f;

    for (int k0 = 0; k0 < D_MODEL; k0 += BK) {
        // Cooperative tile load: 1024 float4 per matrix, 4 per thread.
#pragma unroll
        for (int i = 0; i < 4; i++) {
            int idx = tid + i * TPB;       // 0..1023
            int r   = idx >> 3;            // 0..127
            int c4  = idx & 7;             // 0..7
            int c   = c4 * 4;
            float4 va = *(const float4*)(A + (size_t)(row0 + r) * D_MODEL + k0 + c);
            float4 vb = *(const float4*)(B + (size_t)r * D_MODEL + k0 + c);
            As[(c + 0) * BM + r] = va.x;
            As[(c + 1) * BM + r] = va.y;
            As[(c + 2) * BM + r] = va.z;
            As[(c + 3) * BM + r] = va.w;
            Bs[(c + 0) * BN + r] = vb.x;
            Bs[(c + 1) * BN + r] = vb.y;
            Bs[(c + 2) * BN + r] = vb.z;
            Bs[(c + 3) * BN + r] = vb.w;
        }
        __syncthreads();

#pragma unroll 4
        for (int k = 0; k < BK; k++) {
            float a[8], b[8];
#pragma unroll
            for (int i = 0; i < 8; i++) a[i] = As[k * BM + ty * 8 + i];
#pragma unroll
            for (int j = 0; j < 8; j++) b[j] = Bs[k * BN + tx * 8 + j];
#pragma unroll
            for (int i = 0; i < 8; i++)
#pragma unroll
                for (int j = 0; j < 8; j++)
                    acc[i][j] = fmaf(a[i], b[j], acc[i][j]);
        }
        __syncthreads();
    }

    // Dump logits tile to smem for the reduction epilogue
#pragma unroll
    for (int i = 0; i < 8; i++)
#pragma unroll
        for (int j = 0; j < 8; j++)
            Ls[(ty * 8 + i) * BN + tx * 8 + j] = acc[i][j];
    __syncthreads();

    // Epilogue: one warp per token, 8 warps stride over 128 tokens.
    const int wid  = tid >> 5;
    const int lane = tid & 31;
    const float inv_temp = 1.0f / 0.3f;

    for (int t = wid; t < BM; t += 8) {
        float v[4]; int ix[4];
#pragma unroll
        for (int q = 0; q < 4; q++) {
            ix[q] = lane + q * 32;
            v[q]  = Ls[t * BN + ix[q]];
        }
        // Local top-2 over this lane's 4 experts
        float v1 = -INFINITY, v2 = -INFINITY;
        int   i1 = N_EXP, i2 = N_EXP;
#pragma unroll
        for (int q = 0; q < 4; q++) top2_upd(v1, i1, v2, i2, v[q], ix[q]);

        // Butterfly merge -> all lanes hold the global top-2 of 128
#pragma unroll
        for (int off = 16; off > 0; off >>= 1) {
            float ov1 = __shfl_xor_sync(0xffffffffu, v1, off);
            int   oi1 = __shfl_xor_sync(0xffffffffu, i1, off);
            float ov2 = __shfl_xor_sync(0xffffffffu, v2, off);
            int   oi2 = __shfl_xor_sync(0xffffffffu, i2, off);
            top2_upd(v1, i1, v2, i2, ov1, oi1);
            top2_upd(v1, i1, v2, i2, ov2, oi2);
        }

        // Full softmax(logits/0.3) for the load-balance loss (stable: subtract v1)
        float p[4];
        float zl = 0.0f;
#pragma unroll
        for (int q = 0; q < 4; q++) {
            p[q] = expf((v[q] - v1) * inv_temp);
            zl += p[q];
        }
#pragma unroll
        for (int off = 16; off > 0; off >>= 1)
            zl += __shfl_xor_sync(0xffffffffu, zl, off);
        float invZ = 1.0f / zl;
#pragma unroll
        for (int q = 0; q < 4; q++)
            atomicAdd(&sMe[ix[q]], p[q] * invZ);

        if (lane == 0) {
            int tok = row0 + t;
            // top_idx (as float), row-major [T, 2]
            out[tok * 2 + 0] = (float)i1;
            out[tok * 2 + 1] = (float)i2;
            // gate_score = softmax([v1, v2])
            float e  = expf(v2 - v1);       // <= 1
            float g1 = e / (1.0f + e);
            out[2 * T_TOKENS + tok * 2 + 0] = 1.0f - g1;
            out[2 * T_TOKENS + tok * 2 + 1] = g1;
            atomicAdd(&g_ce[i1], 1);
        }
    }
    __syncthreads();
    if (tid < N_EXP) atomicAdd(&g_me[tid], sMe[tid]);
}

__global__ void loss_kernel(float* __restrict__ out) {
    __shared__ float red[N_EXP];
    int i = threadIdx.x;
    red[i] = g_me[i] * (float)g_ce[i];
    __syncthreads();
    for (int s = 64; s > 0; s >>= 1) {
        if (i < s) red[i] += red[i + s];
        __syncthreads();
    }
    if (i == 0) {
        // loss = sum(me * count) * E / T^2
        out[4 * T_TOKENS] = red[0] * ((float)N_EXP /
                              ((float)T_TOKENS * (float)T_TOKENS));
    }
}

extern "C" void kernel_launch(void* const* d_in, const int* in_sizes, int n_in,
                              void* d_out, int out_size) {
    const float* inp = (const float*)d_in[0];
    const float* wg  = (const float*)d_in[1];
    // d_in[2] = top_k (always 2 for this problem) — compile-time specialized.
    float* out = (float*)d_out;

    init_kernel<<<1, 128>>>();

    size_t smem_bytes = (size_t)(BM * BN + N_EXP) * sizeof(float);  // 66048 B
    cudaFuncSetAttribute(gate_kernel,
                         cudaFuncAttributeMaxDynamicSharedMemorySize,
                         (int)smem_bytes);
    gate_kernel<<<T_TOKENS / BM, TPB, smem_bytes>>>(inp, wg, out);

    loss_kernel<<<1, N_EXP>>>(out);
}

// round 4
// speedup vs baseline: 1.9464x; 1.9464x over previous
#include <cuda_runtime.h>
#include <cuda_bf16.h>
#include <math.h>
#include <stdint.h>

// ---------------- Problem constants ----------------
#define T_TOKENS 16384
#define D_MODEL  4096
#define N_EXP    128

// ---------------- GEMM config ----------------
#define BM   128
#define BN   128
#define CK   64                 // K per chunk (64 bf16 = 128B row)
#define NCHUNK (D_MODEL / CK)   // 64
#define TPB  256                // 8 warps: 2 (M) x 4 (N) warp grid

// smem: two 96KB stages; each: Ah Am Al Bh Bm Bl (16KB each, 128 rows x 128B)
#define STAGE_BYTES 98304
#define OFF_AH 0
#define OFF_AM 16384
#define OFF_AL 32768
#define OFF_BH 49152
#define OFF_BM2 65536
#define OFF_BL 81920
#define SMEM_TOTAL (2 * STAGE_BYTES)   // 196608

#define LS_STRIDE 132
#define SWZ(b) ((b) ^ (((b) >> 3) & 0x70))

// ---------------- sm_80-level PTX helpers (compute_103-safe) ----------------
__device__ __forceinline__ uint32_t smem_to_u32(const void* p) {
    uint32_t a;
    asm("{ .reg .u64 t; cvta.to.shared.u64 t, %1; cvt.u32.u64 %0, t; }"
        : "=r"(a) : "l"(p));
    return a;
}
#define LDSM4(r0, r1, r2, r3, addr) \
    asm volatile("ldmatrix.sync.aligned.m8n8.x4.shared.b16 {%0,%1,%2,%3}, [%4];" \
        : "=r"(r0), "=r"(r1), "=r"(r2), "=r"(r3) : "r"(addr))
#define MMA16816(c, a, b0, b1) \
    asm volatile("mma.sync.aligned.m16n8k16.row.col.f32.bf16.bf16.f32 " \
        "{%0,%1,%2,%3},{%4,%5,%6,%7},{%8,%9},{%0,%1,%2,%3};" \
        : "+f"((c)[0]), "+f"((c)[1]), "+f"((c)[2]), "+f"((c)[3]) \
        : "r"((a)[0]), "r"((a)[1]), "r"((a)[2]), "r"((a)[3]), "r"(b0), "r"(b1))
__device__ __forceinline__ void cp16(uint32_t dst, const void* src) {
    asm volatile("cp.async.cg.shared.global [%0], [%1], 16;"
                 :: "r"(dst), "l"(src));
}
#define CP_COMMIT() asm volatile("cp.async.commit_group;" ::: "memory")
#define CP_WAIT0()  asm volatile("cp.async.wait_group 0;" ::: "memory")

// ---------------- Global scratch ----------------
__device__ float g_me[N_EXP];
__device__ int   g_ce[N_EXP];
__device__ __nv_bfloat16 g_Bh[N_EXP * D_MODEL];
__device__ __nv_bfloat16 g_Bm[N_EXP * D_MODEL];
__device__ __nv_bfloat16 g_Bl[N_EXP * D_MODEL];

__global__ void init_kernel() {
    int i = threadIdx.x;
    if (i < N_EXP) { g_me[i] = 0.0f; g_ce[i] = 0; }
}

// 3-way bf16 split (round-to-nearest at each level)
__device__ __forceinline__ void split3(float f, __nv_bfloat16& h,
                                       __nv_bfloat16& m, __nv_bfloat16& l) {
    h = __float2bfloat16(f);
    float r1 = f - __bfloat162float(h);
    m = __float2bfloat16(r1);
    float r2 = r1 - __bfloat162float(m);
    l = __float2bfloat16(r2);
}
__device__ __forceinline__ uint32_t pack2(__nv_bfloat16 a, __nv_bfloat16 b) {
    return (uint32_t)__bfloat16_as_ushort(a) |
           ((uint32_t)__bfloat16_as_ushort(b) << 16);
}

__global__ void prep_b_kernel(const float* __restrict__ wg) {
    int idx = blockIdx.x * blockDim.x + threadIdx.x;  // 0..131071
    float4 v = ((const float4*)wg)[idx];
    float f[4] = {v.x, v.y, v.z, v.w};
    __nv_bfloat16 h[4], m[4], l[4];
#pragma unroll
    for (int q = 0; q < 4; q++) split3(f[q], h[q], m[q], l[q]);
    ((uint2*)g_Bh)[idx] = make_uint2(pack2(h[0], h[1]), pack2(h[2], h[3]));
    ((uint2*)g_Bm)[idx] = make_uint2(pack2(m[0], m[1]), pack2(m[2], m[3]));
    ((uint2*)g_Bl)[idx] = make_uint2(pack2(l[0], l[1]), pack2(l[2], l[3]));
}

// top-2: (v1,i1) >= (v2,i2); ties -> smaller index (jax top_k semantics)
__device__ __forceinline__ void top2_upd(float& v1, int& i1, float& v2, int& i2,
                                         float v, int i) {
    if (v > v1 || (v == v1 && i < i1)) {
        v2 = v1; i2 = i1; v1 = v; i1 = i;
    } else if (v > v2 || (v == v2 && i < i2)) {
        v2 = v; i2 = i;
    }
}

// ---- fill helpers ----
__device__ __forceinline__ void fill_a_ldg(float4* aval, const float* __restrict__ A,
                                           int row0, int k0, int tid) {
#pragma unroll
    for (int i = 0; i < 8; i++) {
        int idx = tid + i * TPB;
        int r   = idx >> 4;
        int col = (idx & 15) << 2;
        aval[i] = *(const float4*)(A + (size_t)(row0 + r) * D_MODEL + k0 + col);
    }
}
__device__ __forceinline__ void fill_a_store(char* stg, const float4* aval, int tid) {
#pragma unroll
    for (int i = 0; i < 8; i++) {
        int idx = tid + i * TPB;
        int r   = idx >> 4;
        int col = (idx & 15) << 2;
        float f[4] = {aval[i].x, aval[i].y, aval[i].z, aval[i].w};
        __nv_bfloat16 h[4], m[4], l[4];
#pragma unroll
        for (int q = 0; q < 4; q++) split3(f[q], h[q], m[q], l[q]);
        uint32_t sw = SWZ((uint32_t)(r * 128 + col * 2));
        *(uint2*)(stg + OFF_AH + sw) = make_uint2(pack2(h[0], h[1]), pack2(h[2], h[3]));
        *(uint2*)(stg + OFF_AM + sw) = make_uint2(pack2(m[0], m[1]), pack2(m[2], m[3]));
        *(uint2*)(stg + OFF_AL + sw) = make_uint2(pack2(l[0], l[1]), pack2(l[2], l[3]));
    }
}
__device__ __forceinline__ void fill_b_cpasync(uint32_t stg_u, int k0, int tid) {
#pragma unroll
    for (int i = 0; i < 4; i++) {
        int idx = tid + i * TPB;
        int r   = idx >> 3;                // expert 0..127
        int c16 = (idx & 7) * 16;          // byte col in 128B row
        size_t g = (size_t)r * D_MODEL + k0 + (c16 >> 1);
        uint32_t sw = SWZ((uint32_t)(r * 128 + c16));
        cp16(stg_u + OFF_BH  + sw, g_Bh + g);
        cp16(stg_u + OFF_BM2 + sw, g_Bm + g);
        cp16(stg_u + OFF_BL  + sw, g_Bl + g);
    }
}

__global__ void __launch_bounds__(TPB, 1)
gate_kernel(const float* __restrict__ A, float* __restrict__ out) {
    extern __shared__ char smem[];
    const uint32_t smem_u = smem_to_u32(smem);
    const int tid  = threadIdx.x;
    const int wid  = tid >> 5;
    const int lane = tid & 31;
    const int row0 = blockIdx.x * BM;
    const int mw = wid >> 2;          // 0..1  -> M offset 64*mw
    const int nw = wid & 3;           // 0..3  -> N offset 32*nw
    const int gid = lane >> 2, tig = lane & 3;

    // ldmatrix per-lane address components
    const int a_mrow = (lane & 7) + ((lane >> 3) & 1) * 8;
    const int a_cofs = ((lane >> 4) & 1) * 16;
    const int b_nrow = (lane & 7) + ((lane >> 4) & 1) * 8;
    const int b_cofs = ((lane >> 3) & 1) * 16;

    float acc[4][4][4];
#pragma unroll
    for (int i = 0; i < 4; i++)
#pragma unroll
        for (int j = 0; j < 4; j++)
#pragma unroll
            for (int q = 0; q < 4; q++) acc[i][j][q] = 0.0f;

    float4 aval[8];

    // ---- prologue: fill stage 0 with chunk 0 ----
    fill_a_ldg(aval, A, row0, 0, tid);
    fill_b_cpasync(smem_u, 0, tid);
    CP_COMMIT();
    fill_a_store(smem, aval, tid);
    CP_WAIT0();
    __syncthreads();

    const int aoff[3] = {OFF_AH, OFF_AM, OFF_AL};
    const int boff[3] = {OFF_BH, OFF_BM2, OFF_BL};

    for (int c = 0; c < NCHUNK; c++) {
        const int sc = c & 1, sf = sc ^ 1;
        const uint32_t cur = smem_u + sc * STAGE_BYTES;

        if (c + 1 < NCHUNK) {
            fill_a_ldg(aval, A, row0, (c + 1) * CK, tid);          // LDG in flight
            fill_b_cpasync(smem_u + sf * STAGE_BYTES, (c + 1) * CK, tid);
            CP_COMMIT();
        }

        // ---- MMA over current stage: K=64 as 4 k16 steps ----
#pragma unroll 1
        for (int ks = 0; ks < 4; ks++) {
            const int kb = ks * 32;
            uint32_t af[3][16];
#pragma unroll
            for (int p = 0; p < 3; p++)
#pragma unroll
                for (int tm = 0; tm < 4; tm++) {
                    uint32_t addr = cur + aoff[p] +
                        SWZ((uint32_t)((mw * 64 + tm * 16 + a_mrow) * 128 + kb + a_cofs));
                    LDSM4(af[p][tm*4+0], af[p][tm*4+1], af[p][tm*4+2], af[p][tm*4+3], addr);
                }
#pragma unroll
            for (int bp = 0; bp < 3; bp++) {
                uint32_t bf[8];
#pragma unroll
                for (int q = 0; q < 2; q++) {
                    uint32_t addr = cur + boff[bp] +
                        SWZ((uint32_t)((nw * 32 + q * 16 + b_nrow) * 128 + kb + b_cofs));
                    LDSM4(bf[q*4+0], bf[q*4+1], bf[q*4+2], bf[q*4+3], addr);
                }
                const int nap = (bp == 0) ? 3 : (bp == 1 ? 2 : 1);
#pragma unroll
                for (int ap = 0; ap < 3; ap++) {
                    if (ap < nap) {
#pragma unroll
                        for (int tm = 0; tm < 4; tm++)
#pragma unroll
                            for (int tn = 0; tn < 4; tn++) {
                                int bq = (tn >> 1) * 4 + (tn & 1) * 2;
                                MMA16816(acc[tm][tn], &af[ap][tm*4], bf[bq], bf[bq+1]);
                            }
                    }
                }
            }
        }

        if (c + 1 < NCHUNK) {
            fill_a_store(smem + sf * STAGE_BYTES, aval, tid);
            CP_WAIT0();
        }
        __syncthreads();
    }

    // ---- write logits tile to smem (reuse stage memory) ----
    float* Ls  = (float*)smem;
    float* sMe = (float*)(smem + BM * LS_STRIDE * 4);
#pragma unroll
    for (int tm = 0; tm < 4; tm++)
#pragma unroll
        for (int tn = 0; tn < 4; tn++) {
            int r_ = mw * 64 + tm * 16 + gid;
            int c_ = nw * 32 + tn * 8 + tig * 2;
            Ls[r_ * LS_STRIDE + c_]           = acc[tm][tn][0];
            Ls[r_ * LS_STRIDE + c_ + 1]       = acc[tm][tn][1];
            Ls[(r_ + 8) * LS_STRIDE + c_]     = acc[tm][tn][2];
            Ls[(r_ + 8) * LS_STRIDE + c_ + 1] = acc[tm][tn][3];
        }
    if (tid < N_EXP) sMe[tid] = 0.0f;
    __syncthreads();

    // ---- epilogue: one warp per token (validated round-1 code) ----
    const float inv_temp = 1.0f / 0.3f;
    for (int t = wid; t < BM; t += 8) {
        float v[4]; int ix[4];
#pragma unroll
        for (int q = 0; q < 4; q++) {
            ix[q] = lane + q * 32;
            v[q]  = Ls[t * LS_STRIDE + ix[q]];
        }
        float v1 = -INFINITY, v2 = -INFINITY;
        int   i1 = N_EXP, i2 = N_EXP;
#pragma unroll
        for (int q = 0; q < 4; q++) top2_upd(v1, i1, v2, i2, v[q], ix[q]);
#pragma unroll
        for (int off = 16; off > 0; off >>= 1) {
            float ov1 = __shfl_xor_sync(0xffffffffu, v1, off);
            int   oi1 = __shfl_xor_sync(0xffffffffu, i1, off);
            float ov2 = __shfl_xor_sync(0xffffffffu, v2, off);
            int   oi2 = __shfl_xor_sync(0xffffffffu, i2, off);
            top2_upd(v1, i1, v2, i2, ov1, oi1);
            top2_upd(v1, i1, v2, i2, ov2, oi2);
        }
        float p[4], zl = 0.0f;
#pragma unroll
        for (int q = 0; q < 4; q++) {
            p[q] = expf((v[q] - v1) * inv_temp);
            zl += p[q];
        }
#pragma unroll
        for (int off = 16; off > 0; off >>= 1)
            zl += __shfl_xor_sync(0xffffffffu, zl, off);
        float invZ = 1.0f / zl;
#pragma unroll
        for (int q = 0; q < 4; q++)
            atomicAdd(&sMe[ix[q]], p[q] * invZ);

        if (lane == 0) {
            int tok = row0 + t;
            out[tok * 2 + 0] = (float)i1;
            out[tok * 2 + 1] = (float)i2;
            float e  = expf(v2 - v1);
            float g1 = e / (1.0f + e);
            out[2 * T_TOKENS + tok * 2 + 0] = 1.0f - g1;
            out[2 * T_TOKENS + tok * 2 + 1] = g1;
            atomicAdd(&g_ce[i1], 1);
        }
    }
    __syncthreads();
    if (tid < N_EXP) atomicAdd(&g_me[tid], sMe[tid]);
}

__global__ void loss_kernel(float* __restrict__ out) {
    __shared__ float red[N_EXP];
    int i = threadIdx.x;
    red[i] = g_me[i] * (float)g_ce[i];
    __syncthreads();
    for (int s = 64; s > 0; s >>= 1) {
        if (i < s) red[i] += red[i + s];
        __syncthreads();
    }
    if (i == 0) {
        out[4 * T_TOKENS] = red[0] * ((float)N_EXP /
                              ((float)T_TOKENS * (float)T_TOKENS));
    }
}

extern "C" void kernel_launch(void* const* d_in, const int* in_sizes, int n_in,
                              void* d_out, int out_size) {
    const float* inp = (const float*)d_in[0];
    const float* wg  = (const float*)d_in[1];
    float* out = (float*)d_out;

    prep_b_kernel<<<(N_EXP * D_MODEL / 4 + 255) / 256, 256>>>(wg);
    init_kernel<<<1, 128>>>();

    cudaFuncSetAttribute(gate_kernel,
                         cudaFuncAttributeMaxDynamicSharedMemorySize,
                         SMEM_TOTAL);
    gate_kernel<<<T_TOKENS / BM, TPB, SMEM_TOTAL>>>(inp, out);

    loss_kernel<<<1, N_EXP>>>(out);
}

// round 5
// speedup vs baseline: 2.3140x; 1.1889x over previous
#include <cuda_runtime.h>
#include <cuda_bf16.h>
#include <math.h>
#include <stdint.h>

// ---------------- Problem constants ----------------
#define T_TOKENS 16384
#define D_MODEL  4096
#define N_EXP    128

// ---------------- GEMM config ----------------
#define BM   128
#define BN   128
#define CK   64                 // K per chunk (64 bf16 = 128B row)
#define NCHUNK (D_MODEL / CK)   // 64
#define TPB  384                // 8 consumer warps (2x4 grid) + 4 producer warps

// smem: two 96KB stages; each: Ah Am Al Bh Bm Bl (16KB each, 128 rows x 128B)
#define STAGE_BYTES 98304
#define OFF_AH 0
#define OFF_AM 16384
#define OFF_AL 32768
#define OFF_BH 49152
#define OFF_BM2 65536
#define OFF_BL 81920
#define SMEM_TOTAL (2 * STAGE_BYTES)   // 196608

#define LS_STRIDE 132
#define SWZ(b) ((b) ^ (((b) >> 3) & 0x70))

// Named barriers (count = all 384 threads)
#define BAR_FULL0  1
#define BAR_FULL1  2
#define BAR_EMPTY0 3
#define BAR_EMPTY1 4
#define BAR_SYNC(id)   asm volatile("bar.sync %0, %1;"   :: "r"(id), "r"(TPB) : "memory")
#define BAR_ARRIVE(id) asm volatile("bar.arrive %0, %1;" :: "r"(id), "r"(TPB) : "memory")

// ---------------- sm_80-level PTX helpers (compute_103-safe) ----------------
__device__ __forceinline__ uint32_t smem_to_u32(const void* p) {
    uint32_t a;
    asm("{ .reg .u64 t; cvta.to.shared.u64 t, %1; cvt.u32.u64 %0, t; }"
        : "=r"(a) : "l"(p));
    return a;
}
#define LDSM4(r0, r1, r2, r3, addr) \
    asm volatile("ldmatrix.sync.aligned.m8n8.x4.shared.b16 {%0,%1,%2,%3}, [%4];" \
        : "=r"(r0), "=r"(r1), "=r"(r2), "=r"(r3) : "r"(addr))
#define MMA16816(c, a, b0, b1) \
    asm volatile("mma.sync.aligned.m16n8k16.row.col.f32.bf16.bf16.f32 " \
        "{%0,%1,%2,%3},{%4,%5,%6,%7},{%8,%9},{%0,%1,%2,%3};" \
        : "+f"((c)[0]), "+f"((c)[1]), "+f"((c)[2]), "+f"((c)[3]) \
        : "r"((a)[0]), "r"((a)[1]), "r"((a)[2]), "r"((a)[3]), "r"(b0), "r"(b1))
__device__ __forceinline__ void cp16(uint32_t dst, const void* src) {
    asm volatile("cp.async.cg.shared.global [%0], [%1], 16;"
                 :: "r"(dst), "l"(src));
}
#define CP_COMMIT() asm volatile("cp.async.commit_group;" ::: "memory")
#define CP_WAIT0()  asm volatile("cp.async.wait_group 0;" ::: "memory")

// ---------------- Global scratch ----------------
__device__ float g_me[N_EXP];
__device__ int   g_ce[N_EXP];
__device__ __nv_bfloat16 g_Bh[N_EXP * D_MODEL];
__device__ __nv_bfloat16 g_Bm[N_EXP * D_MODEL];
__device__ __nv_bfloat16 g_Bl[N_EXP * D_MODEL];

__global__ void init_kernel() {
    int i = threadIdx.x;
    if (i < N_EXP) { g_me[i] = 0.0f; g_ce[i] = 0; }
}

// 3-way bf16 split (round-to-nearest at each level)
__device__ __forceinline__ void split3(float f, __nv_bfloat16& h,
                                       __nv_bfloat16& m, __nv_bfloat16& l) {
    h = __float2bfloat16(f);
    float r1 = f - __bfloat162float(h);
    m = __float2bfloat16(r1);
    float r2 = r1 - __bfloat162float(m);
    l = __float2bfloat16(r2);
}
__device__ __forceinline__ uint32_t pack2(__nv_bfloat16 a, __nv_bfloat16 b) {
    return (uint32_t)__bfloat16_as_ushort(a) |
           ((uint32_t)__bfloat16_as_ushort(b) << 16);
}

__global__ void prep_b_kernel(const float* __restrict__ wg) {
    int idx = blockIdx.x * blockDim.x + threadIdx.x;  // 0..131071
    float4 v = ((const float4*)wg)[idx];
    float f[4] = {v.x, v.y, v.z, v.w};
    __nv_bfloat16 h[4], m[4], l[4];
#pragma unroll
    for (int q = 0; q < 4; q++) split3(f[q], h[q], m[q], l[q]);
    ((uint2*)g_Bh)[idx] = make_uint2(pack2(h[0], h[1]), pack2(h[2], h[3]));
    ((uint2*)g_Bm)[idx] = make_uint2(pack2(m[0], m[1]), pack2(m[2], m[3]));
    ((uint2*)g_Bl)[idx] = make_uint2(pack2(l[0], l[1]), pack2(l[2], l[3]));
}

// top-2: (v1,i1) >= (v2,i2); ties -> smaller index (jax top_k semantics)
__device__ __forceinline__ void top2_upd(float& v1, int& i1, float& v2, int& i2,
                                         float v, int i) {
    if (v > v1 || (v == v1 && i < i1)) {
        v2 = v1; i2 = i1; v1 = v; i1 = i;
    } else if (v > v2 || (v == v2 && i < i2)) {
        v2 = v; i2 = i;
    }
}

__global__ void __launch_bounds__(TPB, 1)
gate_kernel(const float* __restrict__ A, float* __restrict__ out) {
    extern __shared__ char smem[];
    const uint32_t smem_u = smem_to_u32(smem);
    const int tid  = threadIdx.x;
    const int wid  = tid >> 5;
    const int lane = tid & 31;
    const int row0 = blockIdx.x * BM;

    float acc[4][4][4];   // consumer accumulators (live only in consumer path)

    if (wid < 8) {
        // ================= CONSUMERS: 2(M) x 4(N) warp grid =================
        const int mw = wid >> 2;
        const int nw = wid & 3;
        const int a_mrow = (lane & 7) + ((lane >> 3) & 1) * 8;
        const int a_cofs = ((lane >> 4) & 1) * 16;
        const int b_nrow = (lane & 7) + ((lane >> 4) & 1) * 8;
        const int b_cofs = ((lane >> 3) & 1) * 16;

#pragma unroll
        for (int i = 0; i < 4; i++)
#pragma unroll
            for (int j = 0; j < 4; j++)
#pragma unroll
                for (int q = 0; q < 4; q++) acc[i][j][q] = 0.0f;

        const int aoff[3] = {OFF_AH, OFF_AM, OFF_AL};
        const int boff[3] = {OFF_BH, OFF_BM2, OFF_BL};

        for (int c = 0; c < NCHUNK; c++) {
            const int s = c & 1;
            const uint32_t cur = smem_u + s * STAGE_BYTES;
            BAR_SYNC(s == 0 ? BAR_FULL0 : BAR_FULL1);

#pragma unroll 1
            for (int ks = 0; ks < 4; ks++) {
                const int kb = ks * 32;
                uint32_t af[3][16];
#pragma unroll
                for (int p = 0; p < 3; p++)
#pragma unroll
                    for (int tm = 0; tm < 4; tm++) {
                        uint32_t addr = cur + aoff[p] +
                            SWZ((uint32_t)((mw * 64 + tm * 16 + a_mrow) * 128 + kb + a_cofs));
                        LDSM4(af[p][tm*4+0], af[p][tm*4+1], af[p][tm*4+2], af[p][tm*4+3], addr);
                    }
#pragma unroll
                for (int bp = 0; bp < 3; bp++) {
                    uint32_t bf[8];
#pragma unroll
                    for (int q = 0; q < 2; q++) {
                        uint32_t addr = cur + boff[bp] +
                            SWZ((uint32_t)((nw * 32 + q * 16 + b_nrow) * 128 + kb + b_cofs));
                        LDSM4(bf[q*4+0], bf[q*4+1], bf[q*4+2], bf[q*4+3], addr);
                    }
                    const int nap = (bp == 0) ? 3 : (bp == 1 ? 2 : 1);
#pragma unroll
                    for (int ap = 0; ap < 3; ap++) {
                        if (ap < nap) {
#pragma unroll
                            for (int tm = 0; tm < 4; tm++)
#pragma unroll
                                for (int tn = 0; tn < 4; tn++) {
                                    int bq = (tn >> 1) * 4 + (tn & 1) * 2;
                                    MMA16816(acc[tm][tn], &af[ap][tm*4], bf[bq], bf[bq+1]);
                                }
                        }
                    }
                }
            }
            BAR_ARRIVE(s == 0 ? BAR_EMPTY0 : BAR_EMPTY1);
        }
    } else {
        // ================= PRODUCERS: 4 warps, 128 threads =================
        const int ptid = tid - 256;   // 0..127
        for (int c = 0; c < NCHUNK; c++) {
            const int s = c & 1;
            char* stg = smem + s * STAGE_BYTES;
            const uint32_t stg_u = smem_u + s * STAGE_BYTES;
            const int k0 = c * CK;

            if (c >= 2) BAR_SYNC(s == 0 ? BAR_EMPTY0 : BAR_EMPTY1);

            // B tiles via cp.async (in flight during A work)
#pragma unroll
            for (int i = 0; i < 8; i++) {
                int idx = ptid + i * 128;          // 0..1023
                int r   = idx >> 3;
                int c16 = (idx & 7) * 16;
                size_t g = (size_t)r * D_MODEL + k0 + (c16 >> 1);
                uint32_t sw = SWZ((uint32_t)(r * 128 + c16));
                cp16(stg_u + OFF_BH  + sw, g_Bh + g);
                cp16(stg_u + OFF_BM2 + sw, g_Bm + g);
                cp16(stg_u + OFF_BL  + sw, g_Bl + g);
            }
            CP_COMMIT();

            // A: LDG (MLP=16) -> split3 -> STS
            float4 aval[16];
#pragma unroll
            for (int i = 0; i < 16; i++) {
                int idx = ptid + i * 128;          // 0..2047
                int r   = idx >> 4;
                int col = (idx & 15) << 2;
                aval[i] = *(const float4*)(A + (size_t)(row0 + r) * D_MODEL + k0 + col);
            }
#pragma unroll
            for (int i = 0; i < 16; i++) {
                int idx = ptid + i * 128;
                int r   = idx >> 4;
                int col = (idx & 15) << 2;
                float f[4] = {aval[i].x, aval[i].y, aval[i].z, aval[i].w};
                __nv_bfloat16 h[4], m[4], l[4];
#pragma unroll
                for (int q = 0; q < 4; q++) split3(f[q], h[q], m[q], l[q]);
                uint32_t sw = SWZ((uint32_t)(r * 128 + col * 2));
                *(uint2*)(stg + OFF_AH + sw) = make_uint2(pack2(h[0], h[1]), pack2(h[2], h[3]));
                *(uint2*)(stg + OFF_AM + sw) = make_uint2(pack2(m[0], m[1]), pack2(m[2], m[3]));
                *(uint2*)(stg + OFF_AL + sw) = make_uint2(pack2(l[0], l[1]), pack2(l[2], l[3]));
            }
            CP_WAIT0();
            BAR_ARRIVE(s == 0 ? BAR_FULL0 : BAR_FULL1);
        }
    }

    __syncthreads();   // all 384 threads; stages now free -> repurpose as Ls

    float* Ls  = (float*)smem;
    float* sMe = (float*)(smem + BM * LS_STRIDE * 4);

    if (wid < 8) {
        const int mw = wid >> 2, nw = wid & 3;
        const int gid = lane >> 2, tig = lane & 3;
#pragma unroll
        for (int tm = 0; tm < 4; tm++)
#pragma unroll
            for (int tn = 0; tn < 4; tn++) {
                int r_ = mw * 64 + tm * 16 + gid;
                int c_ = nw * 32 + tn * 8 + tig * 2;
                Ls[r_ * LS_STRIDE + c_]           = acc[tm][tn][0];
                Ls[r_ * LS_STRIDE + c_ + 1]       = acc[tm][tn][1];
                Ls[(r_ + 8) * LS_STRIDE + c_]     = acc[tm][tn][2];
                Ls[(r_ + 8) * LS_STRIDE + c_ + 1] = acc[tm][tn][3];
            }
    }
    if (tid >= 256 && tid < 256 + N_EXP) sMe[tid - 256] = 0.0f;
    __syncthreads();

    // ---- epilogue: one warp per token, 12 warps stride over 128 tokens ----
    const float inv_temp = 1.0f / 0.3f;
    for (int t = wid; t < BM; t += 12) {
        float v[4]; int ix[4];
#pragma unroll
        for (int q = 0; q < 4; q++) {
            ix[q] = lane + q * 32;
            v[q]  = Ls[t * LS_STRIDE + ix[q]];
        }
        float v1 = -INFINITY, v2 = -INFINITY;
        int   i1 = N_EXP, i2 = N_EXP;
#pragma unroll
        for (int q = 0; q < 4; q++) top2_upd(v1, i1, v2, i2, v[q], ix[q]);
#pragma unroll
        for (int off = 16; off > 0; off >>= 1) {
            float ov1 = __shfl_xor_sync(0xffffffffu, v1, off);
            int   oi1 = __shfl_xor_sync(0xffffffffu, i1, off);
            float ov2 = __shfl_xor_sync(0xffffffffu, v2, off);
            int   oi2 = __shfl_xor_sync(0xffffffffu, i2, off);
            top2_upd(v1, i1, v2, i2, ov1, oi1);
            top2_upd(v1, i1, v2, i2, ov2, oi2);
        }
        float p[4], zl = 0.0f;
#pragma unroll
        for (int q = 0; q < 4; q++) {
            p[q] = expf((v[q] - v1) * inv_temp);
            zl += p[q];
        }
#pragma unroll
        for (int off = 16; off > 0; off >>= 1)
            zl += __shfl_xor_sync(0xffffffffu, zl, off);
        float invZ = 1.0f / zl;
#pragma unroll
        for (int q = 0; q < 4; q++)
            atomicAdd(&sMe[ix[q]], p[q] * invZ);

        if (lane == 0) {
            int tok = row0 + t;
            out[tok * 2 + 0] = (float)i1;
            out[tok * 2 + 1] = (float)i2;
            float e  = expf(v2 - v1);
            float g1 = e / (1.0f + e);
            out[2 * T_TOKENS + tok * 2 + 0] = 1.0f - g1;
            out[2 * T_TOKENS + tok * 2 + 1] = g1;
            atomicAdd(&g_ce[i1], 1);
        }
    }
    __syncthreads();
    if (tid < N_EXP) atomicAdd(&g_me[tid], sMe[tid]);
}

__global__ void loss_kernel(float* __restrict__ out) {
    __shared__ float red[N_EXP];
    int i = threadIdx.x;
    red[i] = g_me[i] * (float)g_ce[i];
    __syncthreads();
    for (int s = 64; s > 0; s >>= 1) {
        if (i < s) red[i] += red[i + s];
        __syncthreads();
    }
    if (i == 0) {
        out[4 * T_TOKENS] = red[0] * ((float)N_EXP /
                              ((float)T_TOKENS * (float)T_TOKENS));
    }
}

extern "C" void kernel_launch(void* const* d_in, const int* in_sizes, int n_in,
                              void* d_out, int out_size) {
    const float* inp = (const float*)d_in[0];
    const float* wg  = (const float*)d_in[1];
    float* out = (float*)d_out;

    prep_b_kernel<<<(N_EXP * D_MODEL / 4 + 255) / 256, 256>>>(wg);
    init_kernel<<<1, 128>>>();

    cudaFuncSetAttribute(gate_kernel,
                         cudaFuncAttributeMaxDynamicSharedMemorySize,
                         SMEM_TOTAL);
    gate_kernel<<<T_TOKENS / BM, TPB, SMEM_TOTAL>>>(inp, out);

    loss_kernel<<<1, N_EXP>>>(out);
}